// round 14
// baseline (speedup 1.0000x reference)
#include <cuda_runtime.h>

// 2-layer LSTM + linear head + clip. B=256 T=2048 I=32 H=64.
// K1: xg[b][t][row] = x@Wih0^T + biases (parallel, coalesced [b][t] layout).
// K2: 128 CTAs x 256 thr (255-reg budget), CTA = 2 batches, persistent.
//   LAG-PIPELINED: iteration t computes h1(t) AND h2(t-1); both GEMMs' inputs
//   are ready at iteration top -> merged FMA stream, reductions overlap the
//   other phase's FMA, ONE barrier per iteration.
//   L1: thread owns FULL gate row r1=(q<<6)|u (32 packs), both batches;
//       gather = 8 shfl in the 4-lane quad of unit u=tid>>2.
//   L2: thread owns row pair rA=2gp*64+u, rB=rA+64 x one matrix (kk=0:Wih1 /
//       kk=1:Whh1; 64 packs) x both batches; xor(1) reduce-scatter (keep batch
//       kk) + xor(2) activated-gate swap.
//   Buffers: h1 buf bc=(t&1)*128 written, bp read; h2 bc read, bp written.
//   tanh.approx.f32 activations.
// K3: y = h2@Wout + b, clip.

#define TT 2048
#define NB 256
#define NI 32

typedef unsigned long long ull;

__device__ float g_xg[(size_t)NB * TT * 256];   // [b][t][row-permuted]
__device__ float g_h2[(size_t)NB * TT * 64];    // [b][t][h]

__device__ __forceinline__ float tanhapx(float v) {
    float r; asm("tanh.approx.f32 %0, %1;" : "=f"(r) : "f"(v)); return r;
}
__device__ __forceinline__ void fma2(ull& d, ull a, ull b) {
    asm("fma.rn.f32x2 %0, %1, %2, %0;" : "+l"(d) : "l"(a), "l"(b));
}
__device__ __forceinline__ float2 unpk(ull v) {
    float2 r; asm("mov.b64 {%0, %1}, %2;" : "=f"(r.x), "=f"(r.y) : "l"(v)); return r;
}
__device__ __forceinline__ ull pk(float a, float b) {
    ull r; asm("mov.b64 %0, {%1, %2};" : "=l"(r) : "f"(a), "f"(b)); return r;
}
__device__ __forceinline__ float hsum2(ull a, ull b) {
    float2 x = unpk(a), y = unpk(b);
    return (x.x + x.y) + (y.x + y.y);
}
// gates pre-activated: gi,gf,go = sigmoid, gg = tanh
__device__ __forceinline__ float cell_rest(float gi, float gf, float gg, float go, float& c) {
    c = fmaf(gf, c, gi * gg);
    return go * tanhapx(c);
}

// ---------------- Kernel 1: xg precompute ----------------
__global__ void __launch_bounds__(256, 1)
xg_kernel(const float* __restrict__ x,
          const float* __restrict__ Wih0,
          const float* __restrict__ bih0, const float* __restrict__ bhh0)
{
    __shared__ float xt[4][64 * NI];   // 32 KB
    const int tid = threadIdx.x;
    const int t0 = (blockIdx.x & 31) * 64;
    const int b0 = (blockIdx.x >> 5) * 4;
    const int r  = ((tid & 3) << 6) | (tid >> 2);

    #pragma unroll
    for (int b = 0; b < 4; b++) {
        const float4* src = (const float4*)(x + ((size_t)(b0 + b) * TT + t0) * NI);
        float4* dst = (float4*)xt[b];
        for (int i = tid; i < 64 * NI / 4; i += 256) dst[i] = src[i];
    }

    ull w[16];
    {
        const ulonglong2* W = (const ulonglong2*)(Wih0 + r * NI);
        #pragma unroll
        for (int k = 0; k < 8; k++) { ulonglong2 v = W[k]; w[2*k] = v.x; w[2*k+1] = v.y; }
    }
    const float bias = bih0[r] + bhh0[r];
    __syncthreads();

    #pragma unroll
    for (int b = 0; b < 4; b++) {
        // [b][t][row] layout: contiguous 64*256 floats per (b, tile) -> coalesced
        float* dst = g_xg + ((size_t)(b0 + b) * TT + t0) * 256 + tid;
        #pragma unroll 4
        for (int t = 0; t < 64; t++) {
            const ulonglong2* v = (const ulonglong2*)(xt[b] + t * NI);
            ull aA = pk(bias, 0.f), aB = 0ull;
            #pragma unroll
            for (int c = 0; c < 8; c++) {
                ulonglong2 u = v[c];
                fma2(aA, w[2*c],   u.x);
                fma2(aB, w[2*c+1], u.y);
            }
            dst[t * 256] = hsum2(aA, aB);
        }
    }
}

// ---------------- Kernel 2: lag-pipelined recurrent loop (256 threads) ----------------
__global__ void __launch_bounds__(256, 1)
lstm2_kernel(const float* __restrict__ Whh0,
             const float* __restrict__ Wih1, const float* __restrict__ Whh1,
             const float* __restrict__ bih1, const float* __restrict__ bhh1)
{
    // h1: [2 buf][2 batch][64] at 0..255 ; h2: same at 256..511
    __shared__ __align__(16) float actf[512];
    float* h1s = actf;
    float* h2s = actf + 256;

    const int tid  = threadIdx.x;
    const int lane = tid & 31;
    const unsigned FULL = 0xffffffffu;
    const int bb   = blockIdx.x << 1;

    const int q  = tid & 3;            // L1 gate
    const int u  = tid >> 2;           // hidden unit 0..63
    const int qb = lane & ~3;          // quad base
    const int kk = lane & 1;           // L2: matrix (0=Wih1,1=Whh1) + owned batch
    const int gp = (lane >> 1) & 1;    // L2: row pair (i,f)=0 / (g,o)=1

    const int r1 = (q << 6) | u;       // L1 weight row
    const float km1 = (q == 2) ? 1.f : 0.5f;   // act = ms*tanh(km*A)+md
    const float ms1 = (q == 2) ? 1.f : 0.5f;
    const float md1 = (q == 2) ? 0.f : 0.5f;

    const int rA = (2 * gp) * 64 + u;  // gate 2gp
    const int rB = rA + 64;            // gate 2gp+1
    const float kmA = (gp == 1) ? 1.f : 0.5f;  // gate 2 (g) = tanh when gp==1
    const float msA = (gp == 1) ? 1.f : 0.5f;
    const float mdA = (gp == 1) ? 0.f : 0.5f;
    const float biasA = bih1[rA] + bhh1[rA];
    const float biasB = bih1[rB] + bhh1[rB];

    // ---- weights (all registers): L1 32 packs + L2 64 packs ----
    ull w1[32];
    {
        const ulonglong2* W = (const ulonglong2*)(Whh0 + r1 * 64);
        #pragma unroll
        for (int k = 0; k < 16; k++) { ulonglong2 v = W[k]; w1[2*k] = v.x; w1[2*k+1] = v.y; }
    }
    ull wA[32], wB[32];
    {
        const float* Wsrc = kk ? Whh1 : Wih1;
        const ulonglong2* WAp = (const ulonglong2*)(Wsrc + rA * 64);
        const ulonglong2* WBp = (const ulonglong2*)(Wsrc + rB * 64);
        #pragma unroll
        for (int k = 0; k < 16; k++) {
            ulonglong2 va = WAp[k]; wA[2*k] = va.x; wA[2*k+1] = va.y;
            ulonglong2 vb = WBp[k]; wB[2*k] = vb.x; wB[2*k+1] = vb.y;
        }
    }

    for (int i = tid; i < 512; i += 256) actf[i] = 0.f;
    __syncthreads();

    float c10 = 0.f, c11 = 0.f, c2 = 0.f;   // c2: batch kk

    // xg pointers ([b][t][256] layout): batch bb and bb+1
    const float* xgp = g_xg + (size_t)bb * TT * 256 + tid;
    const size_t xgb1 = (size_t)TT * 256;          // offset to batch bb+1
    float* h2w = g_h2 + (size_t)(bb + kk) * TT * 64 + u;   // writer lane ptr

    // iteration t: L1 computes h1(t) (t<TT); L2 computes h2(t-1) (t>0)
    for (int t = 0; t <= TT; ++t) {
        const int bc = (t & 1) << 7;     // buffer written by L1 this iter
        const int bp = bc ^ 128;         // buffer read (h1(t-1)); L2 writes h2 here

        // xg(t) loads issued early; consumed only after the L1 GEMM
        float xg0 = 0.f, xg1 = 0.f;
        if (t < TT) { xg0 = xgp[0]; xg1 = xgp[xgb1]; xgp += 256; }

        // ---- L1 GEMM: W_hh0 . h1(t-1), both batches ----
        ull a0x = 0ull, a0y = 0ull, a1x = 0ull, a1y = 0ull;
        if (t < TT) {
            const float* pb = h1s + bp;
            #pragma unroll
            for (int k = 0; k < 16; k++) {
                ulonglong2 ua = ((const ulonglong2*)pb)[k];          // batch0
                ulonglong2 ub = ((const ulonglong2*)(pb + 64))[k];   // batch1
                fma2(a0x, w1[2*k],   ua.x);
                fma2(a0y, w1[2*k+1], ua.y);
                fma2(a1x, w1[2*k],   ub.x);
                fma2(a1y, w1[2*k+1], ub.y);
            }
        }

        // ---- L2 GEMM: my matrix (kk) applied to h1(t-1) [bp] or h2(t-2) [bc] ----
        ull aA0x = 0ull, aA0y = 0ull, aA1x = 0ull, aA1y = 0ull;
        ull aB0x = 0ull, aB0y = 0ull, aB1x = 0ull, aB1y = 0ull;
        if (t > 0) {
            const float* in = kk ? (h2s + bc) : (h1s + bp);
            #pragma unroll
            for (int k = 0; k < 16; k++) {
                ulonglong2 ua = ((const ulonglong2*)in)[k];          // batch0
                ulonglong2 ub = ((const ulonglong2*)(in + 64))[k];   // batch1
                fma2(aA0x, wA[2*k],   ua.x);
                fma2(aA0y, wA[2*k+1], ua.y);
                fma2(aA1x, wA[2*k],   ub.x);
                fma2(aA1y, wA[2*k+1], ub.y);
                fma2(aB0x, wB[2*k],   ua.x);
                fma2(aB0y, wB[2*k+1], ua.y);
                fma2(aB1x, wB[2*k],   ub.x);
                fma2(aB1y, wB[2*k+1], ub.y);
            }
        }

        // ---- L1 finish: reduce, activate, cell, publish h1(t) ----
        if (t < TT) {
            float A0 = hsum2(a0x, a0y) + xg0;
            float A1 = hsum2(a1x, a1y) + xg1;
            float act0 = fmaf(ms1, tanhapx(km1 * A0), md1);
            float act1 = fmaf(ms1, tanhapx(km1 * A1), md1);
            float gi0 = __shfl_sync(FULL, act0, qb + 0);
            float gf0 = __shfl_sync(FULL, act0, qb + 1);
            float gg0 = __shfl_sync(FULL, act0, qb + 2);
            float go0 = __shfl_sync(FULL, act0, qb + 3);
            float gi1 = __shfl_sync(FULL, act1, qb + 0);
            float gf1 = __shfl_sync(FULL, act1, qb + 1);
            float gg1 = __shfl_sync(FULL, act1, qb + 2);
            float go1 = __shfl_sync(FULL, act1, qb + 3);
            float h10 = cell_rest(gi0, gf0, gg0, go0, c10);
            float h11 = cell_rest(gi1, gf1, gg1, go1, c11);
            if (q == 0) { h1s[bc + u] = h10; h1s[bc + 64 + u] = h11; }
        }

        // ---- L2 finish: reduce across matrices, activate, cell, publish h2(t-1) ----
        if (t > 0) {
            float SA0 = hsum2(aA0x, aA0y);   // row A, batch0 (my matrix half)
            float SA1 = hsum2(aA1x, aA1y);
            float SB0 = hsum2(aB0x, aB0y);
            float SB1 = hsum2(aB1x, aB1y);
            // xor(1) reduce-scatter over matrices: keep batch kk
            float sndA = kk ? SA0 : SA1;
            float sndB = kk ? SB0 : SB1;
            float rcvA = __shfl_xor_sync(FULL, sndA, 1);
            float rcvB = __shfl_xor_sync(FULL, sndB, 1);
            float FA = (kk ? SA1 : SA0) + rcvA + biasA;
            float FB = (kk ? SB1 : SB0) + rcvB + biasB;
            float actA = fmaf(msA, tanhapx(kmA * FA), mdA);          // gate 2gp
            float actB = fmaf(0.5f, tanhapx(0.5f * FB), 0.5f);       // gate 2gp+1 (sigmoid)
            // xor(2): swap activated gate pair with other row-pair lane (same batch)
            float rA2 = __shfl_xor_sync(FULL, actA, 2);
            float rB2 = __shfl_xor_sync(FULL, actB, 2);
            float Gi = gp ? rA2  : actA;
            float Gf = gp ? rB2  : actB;
            float Gg = gp ? actA : rA2;
            float Go = gp ? actB : rB2;
            float h2v = cell_rest(Gi, Gf, Gg, Go, c2);
            if (gp == 0) { h2s[bp + kk * 64 + u] = h2v; *h2w = h2v; }
            h2w += 64;
        }

        __syncthreads();   // single per-iteration barrier
    }
}

// ---------------- Kernel 3: y head ----------------
__global__ void __launch_bounds__(256, 1)
yhead_kernel(const float* __restrict__ Wout, const float* __restrict__ bOut,
             float* __restrict__ out)
{
    __shared__ float w[64];
    __shared__ float bsh;
    if (threadIdx.x < 64) w[threadIdx.x] = Wout[threadIdx.x];
    if (threadIdx.x == 0) bsh = bOut[0];
    __syncthreads();

    int idx = blockIdx.x * 256 + threadIdx.x;     // [b][t]
    const float* hp = g_h2 + (size_t)idx * 64;
    float s = bsh;
    #pragma unroll
    for (int k = 0; k < 16; k++) {
        float4 vv = *(const float4*)(hp + 4 * k);
        s += vv.x * w[4*k] + vv.y * w[4*k+1] + vv.z * w[4*k+2] + vv.w * w[4*k+3];
    }
    out[idx] = fminf(fmaxf(s, 0.f), 1.f);
}

extern "C" void kernel_launch(void* const* d_in, const int* in_sizes, int n_in,
                              void* d_out, int out_size)
{
    (void)in_sizes; (void)n_in; (void)out_size;
    const float* x    = (const float*)d_in[0];
    const float* Wih0 = (const float*)d_in[1];
    const float* Whh0 = (const float*)d_in[2];
    const float* bih0 = (const float*)d_in[3];
    const float* bhh0 = (const float*)d_in[4];
    const float* Wih1 = (const float*)d_in[5];
    const float* Whh1 = (const float*)d_in[6];
    const float* bih1 = (const float*)d_in[7];
    const float* bhh1 = (const float*)d_in[8];
    const float* Wout = (const float*)d_in[9];
    const float* bOut = (const float*)d_in[10];
    float* out = (float*)d_out;

    xg_kernel<<<2048, 256>>>(x, Wih0, bih0, bhh0);
    lstm2_kernel<<<128, 256>>>(Whh0, Wih1, Whh1, bih1, bhh1);
    yhead_kernel<<<2048, 256>>>(Wout, bOut, out);
}

// round 15
// speedup vs baseline: 1.9393x; 1.9393x over previous
#include <cuda_runtime.h>

// 2-layer LSTM + linear head + clip. B=256 T=2048 I=32 H=64.
// K1: xg[t][b][row] = x@Wih0^T + biases (parallel; occupancy-boosted).
// K2: 128 CTAs x 256 thr (255-reg budget), CTA = 2 batches, persistent.
//   == R13 kernel verbatim (proven 2543us). ==
//   Quad of lanes = 4 gates of unit u = tid>>2.
//   L1: thread owns FULL gate row r1=(q<<6)|u (64 cols, 32 packs), both
//       batches; gather = 8 shfl in quad.
//   L2: thread owns row pair rA=2gp*64+u, rB=rA+64 (gates (i,f)|(g,o)) x one
//       matrix (kk=0:Wih1 / kk=1:Whh1, 64 packs) x both batches; xor(1)
//       reduce-scatter (keep batch kk) + xor(2) activated-gate swap.
//   tanh.approx.f32. ONE barrier/step; h1,h2 double-buffered by parity.
// K3: y = h2@Wout + b, clip.

#define TT 2048
#define NB 256
#define NI 32

typedef unsigned long long ull;

__device__ float g_xg[TT * NB * 256];           // [t][b][row-permuted]
__device__ float g_h2[(size_t)NB * TT * 64];    // [b][t][h]

__device__ __forceinline__ float tanhapx(float v) {
    float r; asm("tanh.approx.f32 %0, %1;" : "=f"(r) : "f"(v)); return r;
}
__device__ __forceinline__ void fma2(ull& d, ull a, ull b) {
    asm("fma.rn.f32x2 %0, %1, %2, %0;" : "+l"(d) : "l"(a), "l"(b));
}
__device__ __forceinline__ float2 unpk(ull v) {
    float2 r; asm("mov.b64 {%0, %1}, %2;" : "=f"(r.x), "=f"(r.y) : "l"(v)); return r;
}
__device__ __forceinline__ ull pk(float a, float b) {
    ull r; asm("mov.b64 %0, {%1, %2};" : "=l"(r) : "f"(a), "f"(b)); return r;
}
__device__ __forceinline__ float hsum2(ull a, ull b) {
    float2 x = unpk(a), y = unpk(b);
    return (x.x + x.y) + (y.x + y.y);
}
// gates pre-activated: gi,gf,go = sigmoid, gg = tanh
__device__ __forceinline__ float cell_rest(float gi, float gf, float gg, float go, float& c) {
    c = fmaf(gf, c, gi * gg);
    return go * tanhapx(c);
}

// ---------------- Kernel 1: xg precompute (occupancy-boosted) ----------------
__global__ void __launch_bounds__(256, 3)
xg_kernel(const float* __restrict__ x,
          const float* __restrict__ Wih0,
          const float* __restrict__ bih0, const float* __restrict__ bhh0)
{
    __shared__ float xt[4][64 * NI];   // 32 KB
    const int tid = threadIdx.x;
    const int t0 = (blockIdx.x & 31) * 64;
    const int b0 = (blockIdx.x >> 5) * 4;
    const int r  = ((tid & 3) << 6) | (tid >> 2);

    #pragma unroll
    for (int b = 0; b < 4; b++) {
        const float4* src = (const float4*)(x + ((size_t)(b0 + b) * TT + t0) * NI);
        float4* dst = (float4*)xt[b];
        for (int i = tid; i < 64 * NI / 4; i += 256) dst[i] = src[i];
    }

    ull w[16];
    {
        const ulonglong2* W = (const ulonglong2*)(Wih0 + r * NI);
        #pragma unroll
        for (int k = 0; k < 8; k++) { ulonglong2 v = W[k]; w[2*k] = v.x; w[2*k+1] = v.y; }
    }
    const float bias = bih0[r] + bhh0[r];
    __syncthreads();

    #pragma unroll
    for (int b = 0; b < 4; b++) {
        float* dst = g_xg + ((size_t)t0 * NB + (b0 + b)) * 256 + tid;
        #pragma unroll 4
        for (int t = 0; t < 64; t++) {
            const ulonglong2* v = (const ulonglong2*)(xt[b] + t * NI);
            ull aA = pk(bias, 0.f), aB = 0ull;
            #pragma unroll
            for (int c = 0; c < 8; c++) {
                ulonglong2 u = v[c];
                fma2(aA, w[2*c],   u.x);
                fma2(aB, w[2*c+1], u.y);
            }
            dst[(size_t)t * NB * 256] = hsum2(aA, aB);
        }
    }
}

// ---------------- Kernel 2: recurrent loop (R13 verbatim) ----------------
__global__ void __launch_bounds__(256, 1)
lstm2_kernel(const float* __restrict__ Whh0,
             const float* __restrict__ Wih1, const float* __restrict__ Whh1,
             const float* __restrict__ bih1, const float* __restrict__ bhh1)
{
    // h1: [2 buf][2 batch][64] at 0..255 ; h2: same at 256..511
    __shared__ __align__(16) float actf[512];
    float* h1s = actf;
    float* h2s = actf + 256;

    const int tid  = threadIdx.x;
    const int lane = tid & 31;
    const unsigned FULL = 0xffffffffu;
    const int bb   = blockIdx.x << 1;

    const int q  = tid & 3;            // L1 gate
    const int u  = tid >> 2;           // hidden unit 0..63
    const int qb = lane & ~3;          // quad base
    const int kk = lane & 1;           // L2: matrix (0=Wih1,1=Whh1) + owned batch
    const int gp = (lane >> 1) & 1;    // L2: row pair (i,f)=0 / (g,o)=1

    const int r1 = (q << 6) | u;       // L1 weight row
    const float km1 = (q == 2) ? 1.f : 0.5f;   // act = ms*tanh(km*A)+md
    const float ms1 = (q == 2) ? 1.f : 0.5f;
    const float md1 = (q == 2) ? 0.f : 0.5f;

    const int rA = (2 * gp) * 64 + u;  // gate 2gp
    const int rB = rA + 64;            // gate 2gp+1
    const float kmA = (gp == 1) ? 1.f : 0.5f;  // gate 2 (g) = tanh when gp==1
    const float msA = (gp == 1) ? 1.f : 0.5f;
    const float mdA = (gp == 1) ? 0.f : 0.5f;
    const float biasA = bih1[rA] + bhh1[rA];
    const float biasB = bih1[rB] + bhh1[rB];

    // ---- weights (all registers): L1 32 packs + L2 64 packs ----
    ull w1[32];
    {
        const ulonglong2* W = (const ulonglong2*)(Whh0 + r1 * 64);
        #pragma unroll
        for (int k = 0; k < 16; k++) { ulonglong2 v = W[k]; w1[2*k] = v.x; w1[2*k+1] = v.y; }
    }
    ull wA[32], wB[32];
    {
        const float* Wsrc = kk ? Whh1 : Wih1;
        const ulonglong2* WAp = (const ulonglong2*)(Wsrc + rA * 64);
        const ulonglong2* WBp = (const ulonglong2*)(Wsrc + rB * 64);
        #pragma unroll
        for (int k = 0; k < 16; k++) {
            ulonglong2 va = WAp[k]; wA[2*k] = va.x; wA[2*k+1] = va.y;
            ulonglong2 vb = WBp[k]; wB[2*k] = vb.x; wB[2*k+1] = vb.y;
        }
    }

    for (int i = tid; i < 512; i += 256) actf[i] = 0.f;
    __syncthreads();

    float c10 = 0.f, c11 = 0.f, c2 = 0.f;   // c2: batch kk

    // xg: thread tid reads g_xg[t][b][tid] (row permutation matches xg_kernel)
    float xc0 = g_xg[(size_t)bb * 256 + tid];
    float xc1 = g_xg[((size_t)bb + 1) * 256 + tid];
    const float* gxp = g_xg + ((size_t)NB + bb) * 256 + tid;   // t = 1
    float* h2w = g_h2 + (size_t)(bb + kk) * TT * 64 + u;       // writer lane ptr

    for (int t = 0; t < TT; ++t) {
        float xn0 = 0.f, xn1 = 0.f;
        if (t + 1 < TT) { xn0 = gxp[0]; xn1 = gxp[256]; }
        gxp += NB * 256;

        const int bc = (t & 1) << 7;     // CUR buffer offset
        const int bp = bc ^ 128;         // PRV buffer offset

        // ---- layer 1: h1(t) = cell(W_hh0 . h1(t-1) + xg(t)) ----
        {
            const float* pb = h1s + bp;
            ull a0x = pk(xc0, 0.f), a0y = 0ull;
            ull a1x = pk(xc1, 0.f), a1y = 0ull;
            #pragma unroll
            for (int k = 0; k < 16; k++) {
                ulonglong2 ua = ((const ulonglong2*)pb)[k];          // batch0
                ulonglong2 ub = ((const ulonglong2*)(pb + 64))[k];   // batch1
                fma2(a0x, w1[2*k],   ua.x);
                fma2(a0y, w1[2*k+1], ua.y);
                fma2(a1x, w1[2*k],   ub.x);
                fma2(a1y, w1[2*k+1], ub.y);
            }
            float A0 = hsum2(a0x, a0y);
            float A1 = hsum2(a1x, a1y);
            float act0 = fmaf(ms1, tanhapx(km1 * A0), md1);
            float act1 = fmaf(ms1, tanhapx(km1 * A1), md1);
            float gi0 = __shfl_sync(FULL, act0, qb + 0);
            float gf0 = __shfl_sync(FULL, act0, qb + 1);
            float gg0 = __shfl_sync(FULL, act0, qb + 2);
            float go0 = __shfl_sync(FULL, act0, qb + 3);
            float gi1 = __shfl_sync(FULL, act1, qb + 0);
            float gf1 = __shfl_sync(FULL, act1, qb + 1);
            float gg1 = __shfl_sync(FULL, act1, qb + 2);
            float go1 = __shfl_sync(FULL, act1, qb + 3);
            float h10 = cell_rest(gi0, gf0, gg0, go0, c10);
            float h11 = cell_rest(gi1, gf1, gg1, go1, c11);
            if (q == 0) { h1s[bc + u] = h10; h1s[bc + 64 + u] = h11; }
        }

        __syncthreads();   // single per-step barrier

        // ---- layer 2: h2(t) = cell(Wih1 . h1(t) + Whh1 . h2(t-1)) ----
        {
            const float* in = kk ? (h2s + bp) : (h1s + bc);
            ull aA0x = 0ull, aA0y = 0ull, aA1x = 0ull, aA1y = 0ull;
            ull aB0x = 0ull, aB0y = 0ull, aB1x = 0ull, aB1y = 0ull;
            #pragma unroll
            for (int k = 0; k < 16; k++) {
                ulonglong2 ua = ((const ulonglong2*)in)[k];          // batch0
                ulonglong2 ub = ((const ulonglong2*)(in + 64))[k];   // batch1
                fma2(aA0x, wA[2*k],   ua.x);
                fma2(aA0y, wA[2*k+1], ua.y);
                fma2(aA1x, wA[2*k],   ub.x);
                fma2(aA1y, wA[2*k+1], ub.y);
                fma2(aB0x, wB[2*k],   ua.x);
                fma2(aB0y, wB[2*k+1], ua.y);
                fma2(aB1x, wB[2*k],   ub.x);
                fma2(aB1y, wB[2*k+1], ub.y);
            }
            float SA0 = hsum2(aA0x, aA0y);   // row A, batch0 (my matrix half)
            float SA1 = hsum2(aA1x, aA1y);
            float SB0 = hsum2(aB0x, aB0y);
            float SB1 = hsum2(aB1x, aB1y);
            // xor(1) reduce-scatter over matrices: keep batch kk
            float sndA = kk ? SA0 : SA1;     // my partial for batch kk^1
            float sndB = kk ? SB0 : SB1;
            float rcvA = __shfl_xor_sync(FULL, sndA, 1);
            float rcvB = __shfl_xor_sync(FULL, sndB, 1);
            float FA = (kk ? SA1 : SA0) + rcvA + biasA;
            float FB = (kk ? SB1 : SB0) + rcvB + biasB;
            float actA = fmaf(msA, tanhapx(kmA * FA), mdA);          // gate 2gp
            float actB = fmaf(0.5f, tanhapx(0.5f * FB), 0.5f);       // gate 2gp+1 (sigmoid)
            // xor(2): swap activated gate pair with other row-pair lane (same batch)
            float rA2 = __shfl_xor_sync(FULL, actA, 2);
            float rB2 = __shfl_xor_sync(FULL, actB, 2);
            float Gi = gp ? rA2  : actA;
            float Gf = gp ? rB2  : actB;
            float Gg = gp ? actA : rA2;
            float Go = gp ? actB : rB2;
            float h2v = cell_rest(Gi, Gf, Gg, Go, c2);
            if (gp == 0) { h2s[bc + kk * 64 + u] = h2v; *h2w = h2v; }
            h2w += 64;
        }

        xc0 = xn0; xc1 = xn1;
    }
}

// ---------------- Kernel 3: y head ----------------
__global__ void __launch_bounds__(256, 1)
yhead_kernel(const float* __restrict__ Wout, const float* __restrict__ bOut,
             float* __restrict__ out)
{
    __shared__ float w[64];
    __shared__ float bsh;
    if (threadIdx.x < 64) w[threadIdx.x] = Wout[threadIdx.x];
    if (threadIdx.x == 0) bsh = bOut[0];
    __syncthreads();

    int idx = blockIdx.x * 256 + threadIdx.x;     // [b][t]
    const float* hp = g_h2 + (size_t)idx * 64;
    float s = bsh;
    #pragma unroll
    for (int k = 0; k < 16; k++) {
        float4 vv = *(const float4*)(hp + 4 * k);
        s += vv.x * w[4*k] + vv.y * w[4*k+1] + vv.z * w[4*k+2] + vv.w * w[4*k+3];
    }
    out[idx] = fminf(fmaxf(s, 0.f), 1.f);
}

extern "C" void kernel_launch(void* const* d_in, const int* in_sizes, int n_in,
                              void* d_out, int out_size)
{
    (void)in_sizes; (void)n_in; (void)out_size;
    const float* x    = (const float*)d_in[0];
    const float* Wih0 = (const float*)d_in[1];
    const float* Whh0 = (const float*)d_in[2];
    const float* bih0 = (const float*)d_in[3];
    const float* bhh0 = (const float*)d_in[4];
    const float* Wih1 = (const float*)d_in[5];
    const float* Whh1 = (const float*)d_in[6];
    const float* bih1 = (const float*)d_in[7];
    const float* bhh1 = (const float*)d_in[8];
    const float* Wout = (const float*)d_in[9];
    const float* bOut = (const float*)d_in[10];
    float* out = (float*)d_out;

    xg_kernel<<<2048, 256>>>(x, Wih0, bih0, bhh0);
    lstm2_kernel<<<128, 256>>>(Whh0, Wih1, Whh1, bih1, bhh1);
    yhead_kernel<<<2048, 256>>>(Wout, bOut, out);
}